// round 7
// baseline (speedup 1.0000x reference)
#include <cuda_runtime.h>

typedef unsigned long long u64;
typedef unsigned int u32;

#define TT   64
#define BSS  64
#define DIMM 1024
#define G4   4096
#define SRCN 512

// ---------------- scratch (static device globals; no runtime alloc) ----------
__device__ float g_X [TT*BSS*G4];     // 64 MB: pre-activations X[t,b,4096]
__device__ float g_H [TT*BSS*DIMM];   // 16 MB: hidden history H[t,b,1024]
__device__ float g_Q [TT*BSS*DIMM];   // 16 MB: encoder queries
__device__ float g_QD[TT*BSS*DIMM];   // 16 MB: decoder queries
__device__ float g_E [BSS*TT*SRCN];   //  8 MB: enc scores -> sc -> alpha (in place)
__device__ float g_ED[BSS*TT*TT];     //  1 MB: dec scores -> alpha (in place)
__device__ float g_c [BSS*DIMM];      // cell state
__device__ float g_G [BSS*G4];        //  1 MB: per-step gate pre-activations

// grid barrier state (self-resetting: even #barriers per launch)
__device__ unsigned g_barcnt;
__device__ volatile unsigned g_barsense;

// ---------------- f32x2 packed helpers --------------------------------------
__device__ __forceinline__ void fma2(u64& a, u64 x, u64 y){
    asm("fma.rn.f32x2 %0, %1, %2, %0;" : "+l"(a) : "l"(x), "l"(y));
}
__device__ __forceinline__ u64 dup2(float f){
    u32 u = __float_as_uint(f);
    u64 r; asm("mov.b64 %0, {%1, %1};" : "=l"(r) : "r"(u));
    return r;
}
__device__ __forceinline__ float lo32(u64 v){ return __uint_as_float((u32)v); }
__device__ __forceinline__ float hi32(u64 v){ return __uint_as_float((u32)(v>>32)); }

// ---------------- generic 64x64 NT/NN GEMM (unchanged from R5) ---------------
template<bool GATHER, bool BNN>
__global__ void __launch_bounds__(256) gemm64(
    const float* __restrict__ A, long lda, const int* __restrict__ ridx,
    const float* __restrict__ B, long ldb,
    float* __restrict__ C, long ldc, int K,
    const float* __restrict__ bias1, const float* __restrict__ bias2,
    long bsA, long bsB, long bsC)
{
    __shared__ float At[16][68];
    __shared__ float Bt[16][68];
    const int tid = threadIdx.x;
    const int tx = tid & 15, ty = tid >> 4;
    const int m0 = blockIdx.y * 64;
    const int n0 = blockIdx.x * 64;
    const long z = blockIdx.z;

    const int arow = tid >> 2, akq = tid & 3;
    const float* Arow;
    {
        const float* Ab = A + z * bsA;
        long mrow = m0 + arow;
        if (GATHER) mrow = ridx[mrow];
        Arow = Ab + mrow * lda + akq * 4;
    }
    const float* Brow;
    int bk = 0, bnq = 0, brow = 0, bkq = 0;
    {
        const float* Bb = B + z * bsB;
        if (BNN) { bk = tid >> 4; bnq = tid & 15; Brow = Bb + (long)bk * ldb + n0 + bnq * 4; }
        else     { brow = tid >> 2; bkq = tid & 3; Brow = Bb + (long)(n0 + brow) * ldb + bkq * 4; }
    }

    u64 acc[2][4];
    #pragma unroll
    for (int p = 0; p < 2; p++)
        #pragma unroll
        for (int j = 0; j < 4; j++) acc[p][j] = 0ull;

    float4 ra = *(const float4*)(Arow);
    float4 rb = *(const float4*)(Brow);

    for (int k0 = 0; k0 < K; k0 += 16) {
        __syncthreads();
        At[akq*4+0][arow] = ra.x;
        At[akq*4+1][arow] = ra.y;
        At[akq*4+2][arow] = ra.z;
        At[akq*4+3][arow] = ra.w;
        if (BNN) {
            *(float4*)&Bt[bk][bnq*4] = rb;
        } else {
            Bt[bkq*4+0][brow] = rb.x;
            Bt[bkq*4+1][brow] = rb.y;
            Bt[bkq*4+2][brow] = rb.z;
            Bt[bkq*4+3][brow] = rb.w;
        }
        __syncthreads();
        if (k0 + 16 < K) {
            ra = *(const float4*)(Arow + k0 + 16);
            rb = BNN ? *(const float4*)(Brow + (long)(k0 + 16) * ldb)
                     : *(const float4*)(Brow + k0 + 16);
        }
        #pragma unroll
        for (int k = 0; k < 16; k++) {
            u64 a01 = *(const u64*)&At[k][ty*4];
            u64 a23 = *(const u64*)&At[k][ty*4+2];
            float4 bv = *(const float4*)&Bt[k][tx*4];
            u64 b0 = dup2(bv.x), b1 = dup2(bv.y), b2 = dup2(bv.z), b3 = dup2(bv.w);
            fma2(acc[0][0], a01, b0); fma2(acc[1][0], a23, b0);
            fma2(acc[0][1], a01, b1); fma2(acc[1][1], a23, b1);
            fma2(acc[0][2], a01, b2); fma2(acc[1][2], a23, b2);
            fma2(acc[0][3], a01, b3); fma2(acc[1][3], a23, b3);
        }
    }

    float bn[4];
    #pragma unroll
    for (int j = 0; j < 4; j++) {
        int n = n0 + tx*4 + j;
        float v = 0.f;
        if (bias1) v += bias1[n];
        if (bias2) v += bias2[n];
        bn[j] = v;
    }
    float* Cb = C + z * bsC;
    #pragma unroll
    for (int p = 0; p < 2; p++) {
        long mr = m0 + ty*4 + 2*p;
        float4 r0, r1;
        r0.x = lo32(acc[p][0]) + bn[0]; r1.x = hi32(acc[p][0]) + bn[0];
        r0.y = lo32(acc[p][1]) + bn[1]; r1.y = hi32(acc[p][1]) + bn[1];
        r0.z = lo32(acc[p][2]) + bn[2]; r1.z = hi32(acc[p][2]) + bn[2];
        r0.w = lo32(acc[p][3]) + bn[3]; r1.w = hi32(acc[p][3]) + bn[3];
        *(float4*)&Cb[mr * ldc + n0 + tx*4]     = r0;
        *(float4*)&Cb[(mr+1) * ldc + n0 + tx*4] = r1;
    }
}

// ---------------- persistent LSTM: all 64 steps in one kernel ----------------
// 128 blocks (<=148 SMs -> all co-resident), 256 threads.
// Block owns a 32-column slice of W_hh, SMEM-resident (stride 1028 floats).
// Per step: gates GEMM (f32x2, k-pairs packed in SIMD lanes) -> G, grid
// barrier, elementwise LSTM -> c/H[t]/out, grid barrier.
#define WS_STRIDE 1028
#define AT_STRIDE 36

__device__ __forceinline__ void grid_barrier(unsigned& sense){
    __syncthreads();
    if (threadIdx.x == 0){
        sense ^= 1u;
        __threadfence();
        unsigned a = atomicAdd(&g_barcnt, 1u);
        if (a == gridDim.x - 1u){
            g_barcnt = 0u;
            __threadfence();
            g_barsense = sense;
        } else {
            while (g_barsense != sense) __nanosleep(32);
        }
    }
    __syncthreads();
}

__global__ void __launch_bounds__(256) lstm_persist(
    const float* __restrict__ h0, const float* __restrict__ c0,
    const float* __restrict__ Whh, const float* __restrict__ X,
    float* __restrict__ H, float* __restrict__ c,
    float* __restrict__ G, float* __restrict__ out)
{
    extern __shared__ float sm[];
    float* ws = sm;                    // [32][WS_STRIDE]
    float* at = sm + 32*WS_STRIDE;     // [64][AT_STRIDE]

    const int tid = threadIdx.x;
    const int n0  = blockIdx.x * 32;   // global gate-col base for this block
    const int tx  = tid & 15;          // n-pair 0..15
    const int ty  = tid >> 4;          // m-quad 0..15 (batch rows ty*4..+3)

    // load W_hh slice once (coalesced read, strided SMEM store)
    for (int idx = tid; idx < 32*1024; idx += 256){
        int n = idx >> 10, k = idx & 1023;
        ws[n*WS_STRIDE + k] = Whh[(long)(n0 + n)*1024 + k];
    }
    __syncthreads();

    const float* wr0 = ws + (tx*2)   * WS_STRIDE;
    const float* wr1 = ws + (tx*2+1) * WS_STRIDE;
    const int r0 = tid >> 3;           // A staging: rows r0, r0+32
    const int q0 = (tid & 7) * 4;      // k offset within chunk

    const int gid = blockIdx.x * 256 + tid;   // elementwise work id
    unsigned sense = 0;

    for (int t = 0; t < 64; t++) {
        const float* hp = t ? H + (long)(t-1)*65536 : h0;

        u64 acc[4][2];
        #pragma unroll
        for (int i = 0; i < 4; i++){ acc[i][0] = 0ull; acc[i][1] = 0ull; }

        // prefetch chunk 0 (L2-only loads: data written by other SMs this kernel)
        float4 pa = __ldcg((const float4*)(hp + (long)r0*1024 + q0));
        float4 pb = __ldcg((const float4*)(hp + (long)(r0+32)*1024 + q0));

        for (int kb = 0; kb < 1024; kb += 32) {
            __syncthreads();
            *(float4*)&at[r0*AT_STRIDE + q0]      = pa;
            *(float4*)&at[(r0+32)*AT_STRIDE + q0] = pb;
            __syncthreads();
            if (kb + 32 < 1024) {
                pa = __ldcg((const float4*)(hp + (long)r0*1024 + kb + 32 + q0));
                pb = __ldcg((const float4*)(hp + (long)(r0+32)*1024 + kb + 32 + q0));
            }
            const float* ar = at + (ty*4)*AT_STRIDE;
            #pragma unroll
            for (int kk = 0; kk < 32; kk += 4) {
                u64 b0a = *(const u64*)&wr0[kb+kk];
                u64 b0b = *(const u64*)&wr0[kb+kk+2];
                u64 b1a = *(const u64*)&wr1[kb+kk];
                u64 b1b = *(const u64*)&wr1[kb+kk+2];
                #pragma unroll
                for (int i = 0; i < 4; i++) {
                    u64 a01 = *(const u64*)&ar[i*AT_STRIDE + kk];
                    u64 a23 = *(const u64*)&ar[i*AT_STRIDE + kk+2];
                    fma2(acc[i][0], a01, b0a);
                    fma2(acc[i][0], a23, b0b);
                    fma2(acc[i][1], a01, b1a);
                    fma2(acc[i][1], a23, b1b);
                }
            }
        }

        // write gate pre-activations (even-k lane + odd-k lane)
        {
            int ncol = n0 + tx*2;
            #pragma unroll
            for (int i = 0; i < 4; i++) {
                float2 v;
                v.x = lo32(acc[i][0]) + hi32(acc[i][0]);
                v.y = lo32(acc[i][1]) + hi32(acc[i][1]);
                *(float2*)&G[(long)(ty*4 + i)*4096 + ncol] = v;
            }
        }

        grid_barrier(sense);

        // elementwise LSTM: 16384 float4 items over 32768 threads
        if (gid < 16384) {
            int b  = gid >> 8;
            int dq = (gid & 255) * 4;
            const float* Xr = X + (long)t*262144 + (long)b*4096 + dq;
            float4 gi = __ldcg((const float4*)&G[(long)b*4096 +        dq]);
            float4 gf = __ldcg((const float4*)&G[(long)b*4096 + 1024 + dq]);
            float4 gg = __ldcg((const float4*)&G[(long)b*4096 + 2048 + dq]);
            float4 go = __ldcg((const float4*)&G[(long)b*4096 + 3072 + dq]);
            float4 xi = *(const float4*)(Xr);
            float4 xf = *(const float4*)(Xr + 1024);
            float4 xg = *(const float4*)(Xr + 2048);
            float4 xo = *(const float4*)(Xr + 3072);
            float4 co = t ? __ldcg((const float4*)&c[b*1024 + dq])
                          : *(const float4*)&c0[b*1024 + dq];
            float4 cn, hn;
            #pragma unroll
            for (int j = 0; j < 4; j++) {
                float iv = (&gi.x)[j] + (&xi.x)[j];
                float fv = (&gf.x)[j] + (&xf.x)[j];
                float gv = (&gg.x)[j] + (&xg.x)[j];
                float ov = (&go.x)[j] + (&xo.x)[j];
                float si = 1.f / (1.f + __expf(-iv));
                float sf = 1.f / (1.f + __expf(-fv));
                float so = 1.f / (1.f + __expf(-ov));
                float tg = 2.f / (1.f + __expf(-2.f*gv)) - 1.f;
                float cc = sf * (&co.x)[j] + si * tg;
                float tc = 2.f / (1.f + __expf(-2.f*cc)) - 1.f;
                (&cn.x)[j] = cc;
                (&hn.x)[j] = so * tc;
            }
            *(float4*)&c[b*1024 + dq] = cn;
            *(float4*)&H[(long)t*65536 + b*1024 + dq] = hn;
            *(float4*)&out[(long)t*196608 + (long)b*3072 + dq] = hn;
        }

        grid_barrier(sense);   // also on last step: keeps barrier count even
    }
}

// ---------------- encoder online-softmax scan over t (per (b,n)) ------------
__global__ void __launch_bounds__(256) enc_scan(float* __restrict__ E)
{
    int gid = blockIdx.x * 256 + threadIdx.x;
    int b = gid >> 9, n = gid & 511;
    float m = -1e30f, s = 0.f;
    float* base = E + (long)b * (64*512) + n;
    for (int t = 0; t < 64; t++) {
        float e  = base[t*512];
        float m2 = fmaxf(m, e);
        s = s * __expf(m - m2) + __expf(e - m2);
        float sc = (t == 0) ? e : __expf(e - m2) / s;
        base[t*512] = sc;
        m = m2;
    }
}

// ---------------- row softmax over n=512, in place ---------------------------
__global__ void __launch_bounds__(256) softmax512(float* __restrict__ E)
{
    __shared__ float red[8];
    __shared__ float fin;
    long row = blockIdx.x;
    float* p = E + row * 512;
    int tid = threadIdx.x;
    int lane = tid & 31, wid = tid >> 5;
    float x0 = p[tid], x1 = p[tid + 256];
    float m = fmaxf(x0, x1);
    #pragma unroll
    for (int o = 16; o; o >>= 1) m = fmaxf(m, __shfl_xor_sync(0xffffffffu, m, o));
    if (lane == 0) red[wid] = m;
    __syncthreads();
    if (tid < 32) {
        float v = (lane < 8) ? red[lane] : -1e30f;
        #pragma unroll
        for (int o = 4; o; o >>= 1) v = fmaxf(v, __shfl_xor_sync(0xffffffffu, v, o));
        if (lane == 0) fin = v;
    }
    __syncthreads();
    float M = fin;
    float e0 = __expf(x0 - M), e1 = __expf(x1 - M);
    float s = e0 + e1;
    #pragma unroll
    for (int o = 16; o; o >>= 1) s += __shfl_xor_sync(0xffffffffu, s, o);
    if (lane == 0) red[wid] = s;
    __syncthreads();
    if (tid < 32) {
        float v = (lane < 8) ? red[lane] : 0.f;
        #pragma unroll
        for (int o = 4; o; o >>= 1) v += __shfl_xor_sync(0xffffffffu, v, o);
        if (lane == 0) fin = v;
    }
    __syncthreads();
    float inv = 1.f / fin;
    p[tid]       = e0 * inv;
    p[tid + 256] = e1 * inv;
}

// ---------------- causal decoder softmax over tp (row len 64), in place ------
__global__ void __launch_bounds__(64) softmax_dec(float* __restrict__ ED)
{
    __shared__ float red[2];
    int row = blockIdx.x;        // b*64 + t
    int t = row & 63;
    int tid = threadIdx.x;       // tp
    float* p = ED + (long)row * 64;
    if (t == 0) { p[tid] = 0.f; return; }
    float x = (tid < t) ? p[tid] : -1e30f;
    int lane = tid & 31, wid = tid >> 5;
    float m = x;
    #pragma unroll
    for (int o = 16; o; o >>= 1) m = fmaxf(m, __shfl_xor_sync(0xffffffffu, m, o));
    if (lane == 0) red[wid] = m;
    __syncthreads();
    float M = fmaxf(red[0], red[1]);
    float e = __expf(x - M);
    float s = e;
    #pragma unroll
    for (int o = 16; o; o >>= 1) s += __shfl_xor_sync(0xffffffffu, s, o);
    __syncthreads();
    if (lane == 0) red[wid] = s;
    __syncthreads();
    float S = red[0] + red[1];
    p[tid] = e / S;
}

// ---------------- host driver ------------------------------------------------
extern "C" void kernel_launch(void* const* d_in, const int* in_sizes, int n_in,
                              void* d_out, int out_size)
{
    (void)in_sizes; (void)n_in; (void)out_size;
    const int*   tok   = (const int*)  d_in[0];
    const float* h_e   = (const float*)d_in[1];
    const float* h0    = (const float*)d_in[2];
    const float* c0    = (const float*)d_in[3];
    const float* W_emb = (const float*)d_in[4];
    const float* W_ih  = (const float*)d_in[5];
    const float* W_hh  = (const float*)d_in[6];
    const float* b_ih  = (const float*)d_in[7];
    const float* b_hh  = (const float*)d_in[8];
    const float* W_enc = (const float*)d_in[9];
    const float* b_enc = (const float*)d_in[10];
    const float* W_dec = (const float*)d_in[11];
    const float* b_dec = (const float*)d_in[12];
    float* out = (float*)d_out;

    float *X, *H, *Q, *QD, *E, *ED, *c, *G;
    cudaGetSymbolAddress((void**)&X,  g_X);
    cudaGetSymbolAddress((void**)&H,  g_H);
    cudaGetSymbolAddress((void**)&Q,  g_Q);
    cudaGetSymbolAddress((void**)&QD, g_QD);
    cudaGetSymbolAddress((void**)&E,  g_E);
    cudaGetSymbolAddress((void**)&ED, g_ED);
    cudaGetSymbolAddress((void**)&c,  g_c);
    cudaGetSymbolAddress((void**)&G,  g_G);

    // 1) X[t,b,:] = W_emb[tok] @ W_ih^T + b_ih + b_hh    (M=4096,N=4096,K=512)
    gemm64<true,false><<<dim3(64,64,1),256>>>(W_emb,512,tok, W_ih,512,
                                              X,4096, 512, b_ih,b_hh, 0,0,0);

    // 2) all 64 LSTM steps in ONE persistent kernel (grid-barrier synced)
    const int smem_bytes = (32*WS_STRIDE + 64*AT_STRIDE) * 4;
    cudaFuncSetAttribute(lstm_persist,
                         cudaFuncAttributeMaxDynamicSharedMemorySize, smem_bytes);
    lstm_persist<<<128, 256, smem_bytes>>>(h0, c0, W_hh, X, H, c, G, out);

    // 3) Q = H@W_enc^T + b_enc ; QD = H@W_dec^T + b_dec   (M=4096,N=1024,K=1024)
    gemm64<false,false><<<dim3(16,64,1),256>>>(H,1024,nullptr, W_enc,1024,
                                               Q,1024, 1024, b_enc,nullptr, 0,0,0);
    gemm64<false,false><<<dim3(16,64,1),256>>>(H,1024,nullptr, W_dec,1024,
                                               QD,1024, 1024, b_dec,nullptr, 0,0,0);

    // 4) E[b][t][n] = Q[t,b,:] . h_e[n,b,:]   (per-b NT, M=64,N=512,K=1024)
    gemm64<false,false><<<dim3(8,1,64),256>>>(Q,65536,nullptr, h_e,65536,
                                              E,512, 1024, nullptr,nullptr,
                                              1024,1024,32768);
    // 5) online-softmax scan over t, then row softmax over n (both in place)
    enc_scan<<<128,256>>>(E);
    softmax512<<<4096,256>>>(E);
    // 6) c_e = alpha_e @ h_e  -> out[..., 1024:2048]  (per-b NN, M=64,N=1024,K=512)
    gemm64<false,true><<<dim3(16,1,64),256>>>(E,512,nullptr, h_e,65536,
                                              out+1024,196608, 512, nullptr,nullptr,
                                              32768,1024,3072);

    // 7) ED[b][t][tp] = QD[t,b,:] . H[tp,b,:]   (per-b NT, M=64,N=64,K=1024)
    gemm64<false,false><<<dim3(1,1,64),256>>>(QD,65536,nullptr, H,65536,
                                              ED,64, 1024, nullptr,nullptr,
                                              1024,1024,4096);
    // 8) strictly-causal softmax (zeros at t==0)
    softmax_dec<<<4096,64>>>(ED);
    // 9) cd = alpha_d @ H -> out[..., 2048:3072]  (per-b NN, M=64,N=1024,K=64)
    gemm64<false,true><<<dim3(16,1,64),256>>>(ED,64,nullptr, H,65536,
                                              out+2048,196608, 64, nullptr,nullptr,
                                              4096,1024,3072);
}

// round 8
// speedup vs baseline: 1.3849x; 1.3849x over previous
#include <cuda_runtime.h>

typedef unsigned long long u64;
typedef unsigned int u32;

// ---------------- scratch (static device globals; no runtime alloc) ----------
__device__ float g_X [64*64*4096];    // 64 MB: pre-activations X[t,b,4096]
__device__ float g_H [64*64*1024];    // 16 MB: hidden history H[t,b,1024]
__device__ float g_Q [64*64*1024];    // 16 MB: encoder queries
__device__ float g_QD[64*64*1024];    // 16 MB: decoder queries
__device__ float g_E [64*64*512];     //  8 MB: enc scores -> sc -> alpha (in place)
__device__ float g_ED[64*64*64];      //  1 MB: dec scores -> alpha (in place)
__device__ float g_c [64*1024];       // cell state
__device__ float g_P [8*64*4096];     //  8 MB: K-split partial gate sums

// ---------------- f32x2 packed helpers --------------------------------------
__device__ __forceinline__ void fma2(u64& a, u64 x, u64 y){
    asm("fma.rn.f32x2 %0, %1, %2, %0;" : "+l"(a) : "l"(x), "l"(y));
}
__device__ __forceinline__ u64 dup2(float f){
    u32 u = __float_as_uint(f);
    u64 r; asm("mov.b64 %0, {%1, %1};" : "=l"(r) : "r"(u));
    return r;
}
__device__ __forceinline__ float lo32(u64 v){ return __uint_as_float((u32)v); }
__device__ __forceinline__ float hi32(u64 v){ return __uint_as_float((u32)(v>>32)); }

// ---------------- wide GEMM: 64m x 256n tile, 8x8 per thread -----------------
// C[m,n] = sum_k A[m,k]*B[.,k]  (NT: B[n][k], ldb = n-row stride)
//                                (NN: B[k][n], ldb = k-row stride)
// 256 threads: tx = tid&31 covers n = n0 + tx + 32*j (j=0..7),
//              ty = tid>>5 covers m = ty*8 .. +7 (accs pack m-pairs in f32x2).
// Per k: a = 4 native LDS.64 (warp-uniform), b = 8 strided LDS.32 (+dup2,
// reused x4) -> 16 wavefronts per 32 fma2 = balanced with issue.
// SPLIT: blockIdx.y = K-chunk index (m0 = 0), partials to C + y*64*ldc.
// else : blockIdx.y = m-tile index.
template<bool GATHER, bool BNN, bool SPLIT>
__global__ void __launch_bounds__(256) gemm_wide(
    const float* __restrict__ A, long lda, const int* __restrict__ ridx,
    const float* __restrict__ B, long ldb,
    float* __restrict__ C, long ldc, int K, int kch,
    const float* __restrict__ bias1, const float* __restrict__ bias2,
    long bsA, long bsB, long bsC)
{
    __shared__ float At[16][68];
    __shared__ float Bt[16][260];
    const int tid = threadIdx.x;
    const int tx = tid & 31;
    const int ty = tid >> 5;
    const int n0 = blockIdx.x * 256;
    const long z = blockIdx.z;
    const int m0   = SPLIT ? 0 : blockIdx.y * 64;
    const int kb   = SPLIT ? blockIdx.y * kch : 0;
    const int kcnt = SPLIT ? kch : K;

    // A tile loader: 64 rows x 16 k per chunk, 1 float4/thread
    const int arow = tid >> 2, akq = tid & 3;
    const float* Arow;
    {
        const float* Ab = A + z * bsA;
        long mrow = m0 + arow;
        if (GATHER) mrow = ridx[mrow];
        Arow = Ab + mrow * lda + kb + akq * 4;
    }
    // B tile loaders
    const int brow = tid >> 1, bq = tid & 1;        // NT: rows brow, brow+128
    const float* Brow0 = nullptr; const float* Brow1 = nullptr;
    const int bk = tid >> 4, bn = tid & 15;         // NN: k-row bk, n bn*16..+15
    const float* Bk = nullptr;
    {
        const float* Bb = B + z * bsB;
        if (BNN) Bk = Bb + (long)(kb + bk) * ldb + n0 + bn * 16;
        else {
            Brow0 = Bb + (long)(n0 + brow)       * ldb + kb + bq * 8;
            Brow1 = Bb + (long)(n0 + brow + 128) * ldb + kb + bq * 8;
        }
    }

    u64 acc[4][8];
    #pragma unroll
    for (int i = 0; i < 4; i++)
        #pragma unroll
        for (int j = 0; j < 8; j++) acc[i][j] = 0ull;

    // prefetch chunk 0
    float4 ra = *(const float4*)Arow;
    float4 pb0, pb1, pb2, pb3;
    if (BNN) {
        pb0 = *(const float4*)(Bk);
        pb1 = *(const float4*)(Bk + 4);
        pb2 = *(const float4*)(Bk + 8);
        pb3 = *(const float4*)(Bk + 12);
    } else {
        pb0 = *(const float4*)(Brow0);
        pb1 = *(const float4*)(Brow0 + 4);
        pb2 = *(const float4*)(Brow1);
        pb3 = *(const float4*)(Brow1 + 4);
    }

    for (int k0 = 0; k0 < kcnt; k0 += 16) {
        __syncthreads();
        At[akq*4+0][arow] = ra.x;
        At[akq*4+1][arow] = ra.y;
        At[akq*4+2][arow] = ra.z;
        At[akq*4+3][arow] = ra.w;
        if (BNN) {
            *(float4*)&Bt[bk][bn*16 + 0]  = pb0;
            *(float4*)&Bt[bk][bn*16 + 4]  = pb1;
            *(float4*)&Bt[bk][bn*16 + 8]  = pb2;
            *(float4*)&Bt[bk][bn*16 + 12] = pb3;
        } else {
            Bt[bq*8+0][brow] = pb0.x; Bt[bq*8+1][brow] = pb0.y;
            Bt[bq*8+2][brow] = pb0.z; Bt[bq*8+3][brow] = pb0.w;
            Bt[bq*8+4][brow] = pb1.x; Bt[bq*8+5][brow] = pb1.y;
            Bt[bq*8+6][brow] = pb1.z; Bt[bq*8+7][brow] = pb1.w;
            Bt[bq*8+0][brow+128] = pb2.x; Bt[bq*8+1][brow+128] = pb2.y;
            Bt[bq*8+2][brow+128] = pb2.z; Bt[bq*8+3][brow+128] = pb2.w;
            Bt[bq*8+4][brow+128] = pb3.x; Bt[bq*8+5][brow+128] = pb3.y;
            Bt[bq*8+6][brow+128] = pb3.z; Bt[bq*8+7][brow+128] = pb3.w;
        }
        __syncthreads();
        if (k0 + 16 < kcnt) {
            ra = *(const float4*)(Arow + k0 + 16);
            if (BNN) {
                const float* p = Bk + (long)(k0 + 16) * ldb;
                pb0 = *(const float4*)(p);
                pb1 = *(const float4*)(p + 4);
                pb2 = *(const float4*)(p + 8);
                pb3 = *(const float4*)(p + 12);
            } else {
                pb0 = *(const float4*)(Brow0 + k0 + 16);
                pb1 = *(const float4*)(Brow0 + k0 + 20);
                pb2 = *(const float4*)(Brow1 + k0 + 16);
                pb3 = *(const float4*)(Brow1 + k0 + 20);
            }
        }
        #pragma unroll
        for (int k = 0; k < 16; k++) {
            u64 a0 = *(const u64*)&At[k][ty*8];
            u64 a1 = *(const u64*)&At[k][ty*8+2];
            u64 a2 = *(const u64*)&At[k][ty*8+4];
            u64 a3 = *(const u64*)&At[k][ty*8+6];
            #pragma unroll
            for (int j = 0; j < 8; j++) {
                u64 bd = dup2(Bt[k][tx + 32*j]);
                fma2(acc[0][j], a0, bd);
                fma2(acc[1][j], a1, bd);
                fma2(acc[2][j], a2, bd);
                fma2(acc[3][j], a3, bd);
            }
        }
    }

    float bn8[8];
    #pragma unroll
    for (int j = 0; j < 8; j++) {
        int n = n0 + tx + 32*j;
        float v = 0.f;
        if (bias1) v += bias1[n];
        if (bias2) v += bias2[n];
        bn8[j] = v;
    }
    float* Cb = C + z * bsC + (long)blockIdx.y * 64 * ldc;
    #pragma unroll
    for (int i = 0; i < 4; i++) {
        long r = ty*8 + 2*i;
        #pragma unroll
        for (int j = 0; j < 8; j++) {
            int n = n0 + tx + 32*j;
            Cb[r*ldc + n]     = lo32(acc[i][j]) + bn8[j];
            Cb[(r+1)*ldc + n] = hi32(acc[i][j]) + bn8[j];
        }
    }
}

// ---------------- small 64x64 NT/NN GEMM (R5-proven) for ED / cd -------------
template<bool BNN>
__global__ void __launch_bounds__(256) gemm64(
    const float* __restrict__ A, long lda,
    const float* __restrict__ B, long ldb,
    float* __restrict__ C, long ldc, int K,
    long bsA, long bsB, long bsC)
{
    __shared__ float At[16][68];
    __shared__ float Bt[16][68];
    const int tid = threadIdx.x;
    const int tx = tid & 15, ty = tid >> 4;
    const int m0 = blockIdx.y * 64;
    const int n0 = blockIdx.x * 64;
    const long z = blockIdx.z;

    const int arow = tid >> 2, akq = tid & 3;
    const float* Arow = A + z*bsA + (long)(m0 + arow)*lda + akq*4;
    const float* Brow;
    int bk = 0, bnq = 0, brow = 0, bkq = 0;
    {
        const float* Bb = B + z * bsB;
        if (BNN) { bk = tid >> 4; bnq = tid & 15; Brow = Bb + (long)bk * ldb + n0 + bnq * 4; }
        else     { brow = tid >> 2; bkq = tid & 3; Brow = Bb + (long)(n0 + brow) * ldb + bkq * 4; }
    }

    u64 acc[2][4];
    #pragma unroll
    for (int p = 0; p < 2; p++)
        #pragma unroll
        for (int j = 0; j < 4; j++) acc[p][j] = 0ull;

    float4 ra = *(const float4*)(Arow);
    float4 rb = *(const float4*)(Brow);

    for (int k0 = 0; k0 < K; k0 += 16) {
        __syncthreads();
        At[akq*4+0][arow] = ra.x;
        At[akq*4+1][arow] = ra.y;
        At[akq*4+2][arow] = ra.z;
        At[akq*4+3][arow] = ra.w;
        if (BNN) {
            *(float4*)&Bt[bk][bnq*4] = rb;
        } else {
            Bt[bkq*4+0][brow] = rb.x;
            Bt[bkq*4+1][brow] = rb.y;
            Bt[bkq*4+2][brow] = rb.z;
            Bt[bkq*4+3][brow] = rb.w;
        }
        __syncthreads();
        if (k0 + 16 < K) {
            ra = *(const float4*)(Arow + k0 + 16);
            rb = BNN ? *(const float4*)(Brow + (long)(k0 + 16) * ldb)
                     : *(const float4*)(Brow + k0 + 16);
        }
        #pragma unroll
        for (int k = 0; k < 16; k++) {
            u64 a01 = *(const u64*)&At[k][ty*4];
            u64 a23 = *(const u64*)&At[k][ty*4+2];
            float4 bv = *(const float4*)&Bt[k][tx*4];
            u64 b0 = dup2(bv.x), b1 = dup2(bv.y), b2 = dup2(bv.z), b3 = dup2(bv.w);
            fma2(acc[0][0], a01, b0); fma2(acc[1][0], a23, b0);
            fma2(acc[0][1], a01, b1); fma2(acc[1][1], a23, b1);
            fma2(acc[0][2], a01, b2); fma2(acc[1][2], a23, b2);
            fma2(acc[0][3], a01, b3); fma2(acc[1][3], a23, b3);
        }
    }

    float* Cb = C + z * bsC;
    #pragma unroll
    for (int p = 0; p < 2; p++) {
        long mr = m0 + ty*4 + 2*p;
        float4 r0, r1;
        r0.x = lo32(acc[p][0]); r1.x = hi32(acc[p][0]);
        r0.y = lo32(acc[p][1]); r1.y = hi32(acc[p][1]);
        r0.z = lo32(acc[p][2]); r1.z = hi32(acc[p][2]);
        r0.w = lo32(acc[p][3]); r1.w = hi32(acc[p][3]);
        *(float4*)&Cb[mr * ldc + n0 + tx*4]     = r0;
        *(float4*)&Cb[(mr+1) * ldc + n0 + tx*4] = r1;
    }
}

// ---------------- LSTM stage 2: reduce 8 partials + elementwise --------------
__global__ void __launch_bounds__(128) lstm_fin(
    const float* __restrict__ P, const float* __restrict__ X,
    const float* __restrict__ cprev,
    float* __restrict__ cnew, float* __restrict__ Hout,
    float* __restrict__ outp)
{
    int idx = blockIdx.x * 128 + threadIdx.x;   // 0..16383
    int b  = idx >> 8;
    int dq = (idx & 255) * 4;

    float4 g[4];
    #pragma unroll
    for (int gate = 0; gate < 4; gate++) {
        long off = (long)b * 4096 + gate * 1024 + dq;
        float4 v = *(const float4*)&X[off];
        #pragma unroll
        for (int ks = 0; ks < 8; ks++) {
            float4 p = *(const float4*)&P[(long)ks * (64*4096) + off];
            v.x += p.x; v.y += p.y; v.z += p.z; v.w += p.w;
        }
        g[gate] = v;
    }
    float4 co = *(const float4*)&cprev[b*1024 + dq];
    float4 cn, hn;
    #pragma unroll
    for (int j = 0; j < 4; j++) {
        float iv = (&g[0].x)[j], fv = (&g[1].x)[j], gv = (&g[2].x)[j], ov = (&g[3].x)[j];
        float c_old = (&co.x)[j];
        float si = 1.f / (1.f + __expf(-iv));
        float sf = 1.f / (1.f + __expf(-fv));
        float so = 1.f / (1.f + __expf(-ov));
        float tg = 2.f / (1.f + __expf(-2.f*gv)) - 1.f;
        float cc = sf * c_old + si * tg;
        float tc = 2.f / (1.f + __expf(-2.f*cc)) - 1.f;
        (&cn.x)[j] = cc;
        (&hn.x)[j] = so * tc;
    }
    *(float4*)&cnew[b*1024 + dq] = cn;
    *(float4*)&Hout[b*1024 + dq] = hn;
    *(float4*)&outp[(long)b*3072 + dq] = hn;
}

// ---------------- encoder online-softmax scan over t (per (b,n)) ------------
__global__ void __launch_bounds__(256) enc_scan(float* __restrict__ E)
{
    int gid = blockIdx.x * 256 + threadIdx.x;
    int b = gid >> 9, n = gid & 511;
    float m = -1e30f, s = 0.f;
    float* base = E + (long)b * (64*512) + n;
    for (int t = 0; t < 64; t++) {
        float e  = base[t*512];
        float m2 = fmaxf(m, e);
        s = s * __expf(m - m2) + __expf(e - m2);
        float sc = (t == 0) ? e : __expf(e - m2) / s;
        base[t*512] = sc;
        m = m2;
    }
}

// ---------------- row softmax over n=512, in place ---------------------------
__global__ void __launch_bounds__(256) softmax512(float* __restrict__ E)
{
    __shared__ float red[8];
    __shared__ float fin;
    long row = blockIdx.x;
    float* p = E + row * 512;
    int tid = threadIdx.x;
    int lane = tid & 31, wid = tid >> 5;
    float x0 = p[tid], x1 = p[tid + 256];
    float m = fmaxf(x0, x1);
    #pragma unroll
    for (int o = 16; o; o >>= 1) m = fmaxf(m, __shfl_xor_sync(0xffffffffu, m, o));
    if (lane == 0) red[wid] = m;
    __syncthreads();
    if (tid < 32) {
        float v = (lane < 8) ? red[lane] : -1e30f;
        #pragma unroll
        for (int o = 4; o; o >>= 1) v = fmaxf(v, __shfl_xor_sync(0xffffffffu, v, o));
        if (lane == 0) fin = v;
    }
    __syncthreads();
    float M = fin;
    float e0 = __expf(x0 - M), e1 = __expf(x1 - M);
    float s = e0 + e1;
    #pragma unroll
    for (int o = 16; o; o >>= 1) s += __shfl_xor_sync(0xffffffffu, s, o);
    if (lane == 0) red[wid] = s;
    __syncthreads();
    if (tid < 32) {
        float v = (lane < 8) ? red[lane] : 0.f;
        #pragma unroll
        for (int o = 4; o; o >>= 1) v += __shfl_xor_sync(0xffffffffu, v, o);
        if (lane == 0) fin = v;
    }
    __syncthreads();
    float inv = 1.f / fin;
    p[tid]       = e0 * inv;
    p[tid + 256] = e1 * inv;
}

// ---------------- causal decoder softmax over tp (row len 64), in place ------
__global__ void __launch_bounds__(64) softmax_dec(float* __restrict__ ED)
{
    __shared__ float red[2];
    int row = blockIdx.x;        // b*64 + t
    int t = row & 63;
    int tid = threadIdx.x;       // tp
    float* p = ED + (long)row * 64;
    if (t == 0) { p[tid] = 0.f; return; }
    float x = (tid < t) ? p[tid] : -1e30f;
    int lane = tid & 31, wid = tid >> 5;
    float m = x;
    #pragma unroll
    for (int o = 16; o; o >>= 1) m = fmaxf(m, __shfl_xor_sync(0xffffffffu, m, o));
    if (lane == 0) red[wid] = m;
    __syncthreads();
    float M = fmaxf(red[0], red[1]);
    float e = __expf(x - M);
    float s = e;
    #pragma unroll
    for (int o = 16; o; o >>= 1) s += __shfl_xor_sync(0xffffffffu, s, o);
    __syncthreads();
    if (lane == 0) red[wid] = s;
    __syncthreads();
    float S = red[0] + red[1];
    p[tid] = e / S;
}

// ---------------- host driver ------------------------------------------------
extern "C" void kernel_launch(void* const* d_in, const int* in_sizes, int n_in,
                              void* d_out, int out_size)
{
    (void)in_sizes; (void)n_in; (void)out_size;
    const int*   tok   = (const int*)  d_in[0];
    const float* h_e   = (const float*)d_in[1];
    const float* h0    = (const float*)d_in[2];
    const float* c0    = (const float*)d_in[3];
    const float* W_emb = (const float*)d_in[4];
    const float* W_ih  = (const float*)d_in[5];
    const float* W_hh  = (const float*)d_in[6];
    const float* b_ih  = (const float*)d_in[7];
    const float* b_hh  = (const float*)d_in[8];
    const float* W_enc = (const float*)d_in[9];
    const float* b_enc = (const float*)d_in[10];
    const float* W_dec = (const float*)d_in[11];
    const float* b_dec = (const float*)d_in[12];
    float* out = (float*)d_out;

    float *X, *H, *Q, *QD, *E, *ED, *c, *P;
    cudaGetSymbolAddress((void**)&X,  g_X);
    cudaGetSymbolAddress((void**)&H,  g_H);
    cudaGetSymbolAddress((void**)&Q,  g_Q);
    cudaGetSymbolAddress((void**)&QD, g_QD);
    cudaGetSymbolAddress((void**)&E,  g_E);
    cudaGetSymbolAddress((void**)&ED, g_ED);
    cudaGetSymbolAddress((void**)&c,  g_c);
    cudaGetSymbolAddress((void**)&P,  g_P);

    // 1) X[t,b,:] = W_emb[tok] @ W_ih^T + b_ih + b_hh    (M=4096,N=4096,K=512)
    gemm_wide<true,false,false><<<dim3(16,64,1),256>>>(
        W_emb,512,tok, W_ih,512, X,4096, 512,0, b_ih,b_hh, 0,0,0);

    // 2) sequential LSTM: K-split(8) gates GEMM + reduce/elementwise
    for (int t = 0; t < 64; t++) {
        const float* hprev = t ? H + (long)(t-1)*65536 : h0;
        const float* cprev = t ? c : c0;
        gemm_wide<false,false,true><<<dim3(16,8,1),256>>>(
            hprev,1024,nullptr, W_hh,1024, P,4096, 1024,128,
            nullptr,nullptr, 0,0,0);
        lstm_fin<<<128,128>>>(P, X + (long)t*262144, cprev,
                              c, H + (long)t*65536, out + (long)t*196608);
    }

    // 3) Q = H@W_enc^T + b_enc ; QD = H@W_dec^T + b_dec   (M=4096,N=1024,K=1024)
    gemm_wide<false,false,false><<<dim3(4,64,1),256>>>(
        H,1024,nullptr, W_enc,1024, Q,1024, 1024,0, b_enc,nullptr, 0,0,0);
    gemm_wide<false,false,false><<<dim3(4,64,1),256>>>(
        H,1024,nullptr, W_dec,1024, QD,1024, 1024,0, b_dec,nullptr, 0,0,0);

    // 4) E[b][t][n] = Q[t,b,:] . h_e[n,b,:]   (per-b NT, M=64,N=512,K=1024)
    gemm_wide<false,false,false><<<dim3(2,1,64),256>>>(
        Q,65536,nullptr, h_e,65536, E,512, 1024,0, nullptr,nullptr,
        1024,1024,32768);

    // 5) online-softmax scan over t, then row softmax over n (both in place)
    enc_scan<<<128,256>>>(E);
    softmax512<<<4096,256>>>(E);

    // 6) c_e = alpha_e @ h_e -> out[...,1024:2048]  (per-b NN, M=64,N=1024,K=512)
    gemm_wide<false,true,false><<<dim3(4,1,64),256>>>(
        E,512,nullptr, h_e,65536, out+1024,196608, 512,0, nullptr,nullptr,
        32768,1024,3072);

    // 7) ED[b][t][tp] = QD[t,b,:] . H[tp,b,:]   (per-b NT, M=64,N=64,K=1024)
    gemm64<false><<<dim3(1,1,64),256>>>(QD,65536, H,65536,
                                        ED,64, 1024, 1024,1024,4096);
    // 8) strictly-causal softmax (zeros at t==0)
    softmax_dec<<<4096,64>>>(ED);
    // 9) cd = alpha_d @ H -> out[...,2048:3072]  (per-b NN, M=64,N=1024,K=64)
    gemm64<true><<<dim3(16,1,64),256>>>(ED,64, H,65536,
                                        out+2048,196608, 64, 4096,1024,3072);
}